// round 11
// baseline (speedup 1.0000x reference)
#include <cuda_runtime.h>
#include <cuda_bf16.h>
#include <cstdint>

#define NN 50000
#define EE 600000
#define NPART 196   // ceil(NN/256)

// ---------------- device scratch ----------------
__device__ __align__(16) float g_AB[NN * 128];
__device__ __align__(16) float g_deg[NN];
__device__ __align__(16) float g_dinv[NN];
__device__ __align__(16) float g_xl[NN * 128];
__device__ __align__(16) float g_x1[NN * 128];
__device__ __align__(16) int   g_src[EE];
__device__ __align__(16) int   g_dst[EE];
__device__ __align__(16) int   g_cnt[NN];
__device__ __align__(16) int   g_part[256];
__device__ __align__(16) int   g_row[NN + 1];
__device__ __align__(16) int   g_cur[NN];
__device__ __align__(16) int   g_csrc[EE];
__device__ __align__(16) float g_cw[EE];
// bf16 hi/lo weights, row-major packed bf16x2: [mat][n*64 + colpair]
__device__ __align__(16) unsigned g_Bhi[3][8192];
__device__ __align__(16) unsigned g_Blo[3][8192];

// ---------------- PTX helpers (base PTX only) ----------------
__device__ __forceinline__ void mma_bf16(float* c, const unsigned* a,
                                         unsigned b0, unsigned b1) {
    asm volatile(
        "mma.sync.aligned.m16n8k16.row.col.f32.bf16.bf16.f32 "
        "{%0,%1,%2,%3}, {%4,%5,%6,%7}, {%8,%9}, {%0,%1,%2,%3};"
        : "+f"(c[0]), "+f"(c[1]), "+f"(c[2]), "+f"(c[3])
        : "r"(a[0]), "r"(a[1]), "r"(a[2]), "r"(a[3]), "r"(b0), "r"(b1));
}
__device__ __forceinline__ uint32_t smem_u32(const void* p) {
    uint32_t a;
    asm("{ .reg .u64 t; cvta.to.shared.u64 t, %1; cvt.u32.u64 %0, t; }"
        : "=r"(a) : "l"(p));
    return a;
}
__device__ __forceinline__ void cp_async16(uint32_t dst, const void* src, int nbytes) {
    asm volatile("cp.async.cg.shared.global [%0], [%1], 16, %2;"
                 :: "r"(dst), "l"(src), "r"(nbytes) : "memory");
}
__device__ __forceinline__ void cp_commit() {
    asm volatile("cp.async.commit_group;" ::: "memory");
}
__device__ __forceinline__ void cp_wait0() {
    asm volatile("cp.async.wait_group 0;" ::: "memory");
}

// ---------------- init: zero cnt, deg=1, split-bf16 weights ----------------
__global__ void init_misc(const float* __restrict__ Wp1,
                          const float* __restrict__ W1,
                          const float* __restrict__ W2) {
    if (blockIdx.x < NPART) {
        int i = blockIdx.x * 256 + threadIdx.x;
        if (i < NN) { g_cnt[i] = 0; g_deg[i] = 1.0f; }
        return;
    }
    int idx = (blockIdx.x - NPART) * 256 + threadIdx.x;   // 3*8192 pairs
    if (idx >= 3 * 8192) return;
    int m  = idx >> 13;
    int p  = idx & 8191;
    int n  = p >> 6;
    int k  = (p & 63) * 2;
    float f0, f1;
    if (m == 0) {
        f0 = (n < 64) ? Wp1[n * 256 + k]     : Wp1[(n - 64) * 256 + 128 + k];
        f1 = (n < 64) ? Wp1[n * 256 + k + 1] : Wp1[(n - 64) * 256 + 128 + k + 1];
    } else if (m == 1) { f0 = W1[n * 128 + k]; f1 = W1[n * 128 + k + 1]; }
    else               { f0 = W2[n * 128 + k]; f1 = W2[n * 128 + k + 1]; }
    __nv_bfloat162 h = __floats2bfloat162_rn(f0, f1);
    __nv_bfloat162 l = __floats2bfloat162_rn(f0 - __bfloat162float(h.x),
                                             f1 - __bfloat162float(h.y));
    g_Bhi[m][p] = *(unsigned*)&h;
    g_Blo[m][p] = *(unsigned*)&l;
}

// ---------------- split-bf16 HMMA GEMM, cp.async pipelined ----------------
// Y[M,128] = X[M,128] @ B^T. 32-row tiles. smem (words):
//   stage 4096 | Ah 32*68 | Al 32*68 | Bh 128*68 | Bl 128*68  = 103424 B
#define RS 68
__global__ void __launch_bounds__(256, 2)
gemm_mma(const float* __restrict__ X, const unsigned* __restrict__ Bhi,
         const unsigned* __restrict__ Blo, float* __restrict__ Y, int M) {
    extern __shared__ unsigned sm[];
    float*    St = (float*)sm;                 // 4096 words
    unsigned* Ah = sm + 4096;                  // 32*RS
    unsigned* Al = sm + 4096 + 32 * RS;        // 32*RS
    unsigned* Bh = sm + 4096 + 64 * RS;        // 128*RS
    unsigned* Bl = sm + 4096 + 64 * RS + 128 * RS;
    const uint32_t st_base = smem_u32(St);

    const int tid  = threadIdx.x;
    const int lane = tid & 31;
    const int warp = tid >> 5;
    const int wm = warp & 1;     // 2 m-groups of 16 rows
    const int wn = warp >> 1;    // 4 n-groups of 32 cols
    const int g  = lane >> 2;
    const int tg = lane & 3;

    const int ntiles = (M + 31) >> 5;
    int tile = blockIdx.x;

    // prime: issue cp.async for first tile (overlaps B staging below)
    if (tile < ntiles) {
        #pragma unroll
        for (int k = 0; k < 4; k++) {
            int idx = tid + k * 256;           // float4 units
            int r = idx >> 5, c4 = idx & 31;
            int gr = (tile << 5) + r;
            cp_async16(st_base + idx * 16,
                       X + (size_t)gr * 128 + c4 * 4,
                       (gr < M) ? 16 : 0);
        }
    }
    cp_commit();

    // stage weights (hi+lo)
    #pragma unroll 4
    for (int i = tid; i < 8192; i += 256) {
        int n = i >> 6, cp = i & 63;
        Bh[n * RS + cp] = Bhi[i];
        Bl[n * RS + cp] = Blo[i];
    }

    for (; tile < ntiles; tile += gridDim.x) {
        const int row0 = tile << 5;
        cp_wait0();
        __syncthreads();   // stage ready; prev MMA reads of Ah/Al done

        // convert stage -> Ah/Al (smem only)
        #pragma unroll
        for (int k = 0; k < 8; k++) {
            int idx = tid + k * 256;           // float2 units: 32*64
            int r = idx >> 6, cp = idx & 63;
            float2 f = *(const float2*)&St[idx * 2];
            __nv_bfloat162 h = __floats2bfloat162_rn(f.x, f.y);
            __nv_bfloat162 l = __floats2bfloat162_rn(f.x - __bfloat162float(h.x),
                                                     f.y - __bfloat162float(h.y));
            Ah[r * RS + cp] = *(unsigned*)&h;
            Al[r * RS + cp] = *(unsigned*)&l;
        }
        __syncthreads();   // Ah/Al ready; stage reads done -> safe to refill

        // prefetch next tile into stage (hidden behind MMA below)
        int nxt = tile + gridDim.x;
        if (nxt < ntiles) {
            #pragma unroll
            for (int k = 0; k < 4; k++) {
                int idx = tid + k * 256;
                int r = idx >> 5, c4 = idx & 31;
                int gr = (nxt << 5) + r;
                cp_async16(st_base + idx * 16,
                           X + (size_t)gr * 128 + c4 * 4,
                           (gr < M) ? 16 : 0);
            }
        }
        cp_commit();

        float acc[4][4];
        #pragma unroll
        for (int nt = 0; nt < 4; nt++)
            #pragma unroll
            for (int q = 0; q < 4; q++) acc[nt][q] = 0.f;

        #pragma unroll
        for (int kc = 0; kc < 8; kc++) {
            unsigned ah[4], al[4];
            int w0 = (wm * 16 + g) * RS + kc * 8 + tg;
            ah[0] = Ah[w0];
            ah[1] = Ah[w0 + 8 * RS];
            ah[2] = Ah[w0 + 4];
            ah[3] = Ah[w0 + 8 * RS + 4];
            al[0] = Al[w0];
            al[1] = Al[w0 + 8 * RS];
            al[2] = Al[w0 + 4];
            al[3] = Al[w0 + 8 * RS + 4];
            #pragma unroll
            for (int nt = 0; nt < 4; nt++) {
                int nb = (wn * 32 + nt * 8 + g) * RS + kc * 8 + tg;
                unsigned bh0 = Bh[nb], bh1 = Bh[nb + 4];
                unsigned bl0 = Bl[nb], bl1 = Bl[nb + 4];
                mma_bf16(acc[nt], ah, bh0, bh1);   // hi*hi
                mma_bf16(acc[nt], ah, bl0, bl1);   // hi*lo
                mma_bf16(acc[nt], al, bh0, bh1);   // lo*hi
            }
        }

        // epilogue
        int r = row0 + wm * 16 + g;
        #pragma unroll
        for (int nt = 0; nt < 4; nt++) {
            int c = wn * 32 + nt * 8 + tg * 2;
            if (r < M)
                *(float2*)&Y[(size_t)r * 128 + c] =
                    make_float2(acc[nt][0], acc[nt][1]);
            if (r + 8 < M)
                *(float2*)&Y[(size_t)(r + 8) * 128 + c] =
                    make_float2(acc[nt][2], acc[nt][3]);
        }
    }
}

// ---------------- edge conversion (dtype-robust) + dst histogram ----------------
__global__ void convert_edges(const int* __restrict__ raw) {
    bool is64 = true;
    #pragma unroll
    for (int i = 1; i < 128; i += 2)
        if (raw[i] != 0) { is64 = false; break; }
    int e = blockIdx.x * blockDim.x + threadIdx.x;
    if (e >= EE) return;
    int s, d;
    if (is64) { s = raw[2 * e];  d = raw[2 * (EE + e)]; }
    else      { s = raw[e];      d = raw[EE + e]; }
    g_src[e] = s;
    g_dst[e] = d;
    atomicAdd(&g_cnt[d], 1);
}

// ---------------- 3-kernel exclusive scan ----------------
__global__ void scan_part() {
    __shared__ int sm[256];
    int tid = threadIdx.x;
    int i = blockIdx.x * 256 + tid;
    sm[tid] = (i < NN) ? g_cnt[i] : 0;
    __syncthreads();
    for (int o = 128; o; o >>= 1) {
        if (tid < o) sm[tid] += sm[tid + o];
        __syncthreads();
    }
    if (tid == 0) g_part[blockIdx.x] = sm[0];
}

__global__ void scan_tops() {
    __shared__ int sm[256];
    int tid = threadIdx.x;
    int v = (tid < NPART) ? g_part[tid] : 0;
    sm[tid] = v;
    __syncthreads();
    for (int o = 1; o < 256; o <<= 1) {
        int t = sm[tid] + ((tid >= o) ? sm[tid - o] : 0);
        __syncthreads();
        sm[tid] = t;
        __syncthreads();
    }
    if (tid < NPART) g_part[tid] = sm[tid] - v;
}

__global__ void scan_final() {
    __shared__ int sm[256];
    int tid = threadIdx.x;
    int i = blockIdx.x * 256 + tid;
    int v = (i < NN) ? g_cnt[i] : 0;
    sm[tid] = v;
    __syncthreads();
    for (int o = 1; o < 256; o <<= 1) {
        int t = sm[tid] + ((tid >= o) ? sm[tid - o] : 0);
        __syncthreads();
        sm[tid] = t;
        __syncthreads();
    }
    if (i < NN) {
        int excl = sm[tid] - v + g_part[blockIdx.x];
        g_row[i] = excl;
        g_cur[i] = excl;
    }
    if (i == 0) g_row[NN] = EE;
}

// ------- fused edge pass: ew = sigmoid(relu(A[s]+B[d]+b).w2+b2); CSR fill; deg --
__global__ void edge_fused(const float* __restrict__ b_p1,
                           const float* __restrict__ W_p2,
                           const float* __restrict__ b_p2) {
    int e = (blockIdx.x * blockDim.x + threadIdx.x) >> 5;
    int lane = threadIdx.x & 31;
    if (e >= EE) return;
    int s = g_src[e];
    int d = g_dst[e];
    float2 a  = *(const float2*)&g_AB[(size_t)s * 128 + lane * 2];
    float2 b  = *(const float2*)&g_AB[(size_t)d * 128 + 64 + lane * 2];
    float2 bp = *(const float2*)&b_p1[lane * 2];
    float2 w2 = *(const float2*)&W_p2[lane * 2];
    float h0 = fmaxf(a.x + b.x + bp.x, 0.f);
    float h1 = fmaxf(a.y + b.y + bp.y, 0.f);
    float p = h0 * w2.x + h1 * w2.y;
    #pragma unroll
    for (int o = 16; o; o >>= 1) p += __shfl_xor_sync(0xffffffffu, p, o);
    if (lane == 0) {
        float v = 1.f / (1.f + expf(-(p + b_p2[0])));
        int slot = atomicAdd(&g_cur[d], 1);
        g_csrc[slot] = s;
        g_cw[slot]   = v;
        atomicAdd(&g_deg[d], v);
    }
}

// ---------------- fused dinv + coef: per node ----------------
__global__ void dinv_coef() {
    int n = blockIdx.x * blockDim.x + threadIdx.x;
    if (n >= NN) return;
    float dd = rsqrtf(g_deg[n]);
    g_dinv[n] = dd;
    int e0 = g_row[n], e1 = g_row[n + 1];
    for (int j = e0; j < e1; j++)
        g_cw[j] *= dd * rsqrtf(g_deg[g_csrc[j]]);
}

// ---------------- conv (gather) + relu ----------------
__global__ void conv_relu(const float* __restrict__ bias) {
    int n = blockIdx.x;
    int f = threadIdx.x;
    float di = g_dinv[n];
    float acc = bias[f] + di * di * g_xl[(size_t)n * 128 + f];
    int e0 = g_row[n], e1 = g_row[n + 1];
    for (int j = e0; j < e1; j++) {
        int s = g_csrc[j];
        float c = g_cw[j];
        acc += c * g_xl[(size_t)s * 128 + f];
    }
    g_x1[(size_t)n * 128 + f] = fmaxf(acc, 0.f);
}

// ---------------- conv2 + fused head ----------------
__global__ void conv_head(const float* __restrict__ bias,
                          const float* __restrict__ W_lin,
                          const float* __restrict__ b_lin,
                          float* __restrict__ out) {
    int n = blockIdx.x;
    int f = threadIdx.x;
    float di = g_dinv[n];
    float acc = bias[f] + di * di * g_xl[(size_t)n * 128 + f];
    int e0 = g_row[n], e1 = g_row[n + 1];
    for (int j = e0; j < e1; j++) {
        int s = g_csrc[j];
        float c = g_cw[j];
        acc += c * g_xl[(size_t)s * 128 + f];
    }
    float v = fmaxf(acc, 0.f);
    __shared__ float2 red[128];
    red[f] = make_float2(v * W_lin[f], v * W_lin[128 + f]);
    __syncthreads();
    #pragma unroll
    for (int o = 64; o; o >>= 1) {
        if (f < o) {
            red[f].x += red[f + o].x;
            red[f].y += red[f + o].y;
        }
        __syncthreads();
    }
    if (f == 0) {
        out[2 * n + 0] = 1.f / (1.f + expf(-(red[0].x + b_lin[0])));
        out[2 * n + 1] = 1.f / (1.f + expf(-(red[0].y + b_lin[1])));
    }
}

// ---------------- host ----------------
extern "C" void kernel_launch(void* const* d_in, const int* in_sizes, int n_in,
                              void* d_out, int out_size) {
    const float* x     = (const float*)d_in[0];
    const int*   ei    = (const int*)d_in[1];
    const float* W_p1  = (const float*)d_in[2];
    const float* b_p1  = (const float*)d_in[3];
    const float* W_p2  = (const float*)d_in[4];
    const float* b_p2  = (const float*)d_in[5];
    const float* W1    = (const float*)d_in[6];
    const float* b1    = (const float*)d_in[7];
    const float* W2    = (const float*)d_in[8];
    const float* b2    = (const float*)d_in[9];
    const float* W_lin = (const float*)d_in[10];
    const float* b_lin = (const float*)d_in[11];
    float* out = (float*)d_out;

    void *pAB, *pXL, *pX1, *pBhi, *pBlo;
    cudaGetSymbolAddress(&pAB,  g_AB);
    cudaGetSymbolAddress(&pXL,  g_xl);
    cudaGetSymbolAddress(&pX1,  g_x1);
    cudaGetSymbolAddress(&pBhi, g_Bhi);
    cudaGetSymbolAddress(&pBlo, g_Blo);
    const unsigned* Bhi = (const unsigned*)pBhi;
    const unsigned* Blo = (const unsigned*)pBlo;

    const int MMA_SMEM = (4096 + 64 * RS + 256 * RS) * 4;  // 103424 B -> 2 CTAs/SM
    cudaFuncSetAttribute(gemm_mma, cudaFuncAttributeMaxDynamicSharedMemorySize, MMA_SMEM);

    const int GRID        = 296;
    const int edge_blocks = (EE * 32 + 255) / 256;
    const int e_blocks    = (EE + 255) / 256;
    const int n_blocks    = (NN + 255) / 256;

    init_misc<<<NPART + 96, 256>>>(W_p1, W1, W2);                         // 0
    convert_edges<<<e_blocks, 256>>>(ei);                                 // 1
    scan_part<<<NPART, 256>>>();                                          // 2
    gemm_mma<<<GRID, 256, MMA_SMEM>>>(x, Bhi, Blo, (float*)pAB, NN);      // 3 (profiled)
    scan_tops<<<1, 256>>>();                                              // 4
    scan_final<<<NPART, 256>>>();                                         // 5
    edge_fused<<<edge_blocks, 256>>>(b_p1, W_p2, b_p2);                   // 6
    dinv_coef<<<n_blocks, 256>>>();                                       // 7
    gemm_mma<<<GRID, 256, MMA_SMEM>>>(x, Bhi + 8192, Blo + 8192,
                                      (float*)pXL, NN);                   // 8
    conv_relu<<<NN, 128>>>(b1);                                           // 9
    gemm_mma<<<GRID, 256, MMA_SMEM>>>((const float*)pX1, Bhi + 16384,
                                      Blo + 16384, (float*)pXL, NN);      // 10
    conv_head<<<NN, 128>>>(b2, W_lin, b_lin, out);                        // 11
}

// round 12
// speedup vs baseline: 1.0271x; 1.0271x over previous
#include <cuda_runtime.h>
#include <cuda_bf16.h>
#include <cuda_fp16.h>
#include <cstdint>

#define NN 50000
#define EE 600000
#define NPART 196   // ceil(NN/256)

// ---------------- device scratch ----------------
__device__ __align__(16) float  g_deg[NN];
__device__ __align__(16) float  g_dinv[NN];
__device__ __align__(16) __half g_ABh[NN * 128];   // edge-MLP table (fp16)
__device__ __align__(16) __half g_xlh[NN * 128];   // conv message table (fp16)
__device__ __align__(16) float  g_x1[NN * 128];    // conv1 output (fp32, GEMM input)
__device__ __align__(16) int    g_src[EE];
__device__ __align__(16) int    g_dst[EE];
__device__ __align__(16) int    g_cnt[NN];
__device__ __align__(16) int    g_part[256];
__device__ __align__(16) int    g_row[NN + 1];
__device__ __align__(16) int    g_cur[NN];
__device__ __align__(16) int    g_csrc[EE];
__device__ __align__(16) float  g_cw[EE];
// bf16 hi/lo weights, row-major packed bf16x2: [mat][n*64 + colpair]
__device__ __align__(16) unsigned g_Bhi[3][8192];
__device__ __align__(16) unsigned g_Blo[3][8192];

// ---------------- PTX helpers (base PTX only) ----------------
__device__ __forceinline__ void mma_bf16(float* c, const unsigned* a,
                                         unsigned b0, unsigned b1) {
    asm volatile(
        "mma.sync.aligned.m16n8k16.row.col.f32.bf16.bf16.f32 "
        "{%0,%1,%2,%3}, {%4,%5,%6,%7}, {%8,%9}, {%0,%1,%2,%3};"
        : "+f"(c[0]), "+f"(c[1]), "+f"(c[2]), "+f"(c[3])
        : "r"(a[0]), "r"(a[1]), "r"(a[2]), "r"(a[3]), "r"(b0), "r"(b1));
}
__device__ __forceinline__ uint32_t smem_u32(const void* p) {
    uint32_t a;
    asm("{ .reg .u64 t; cvta.to.shared.u64 t, %1; cvt.u32.u64 %0, t; }"
        : "=r"(a) : "l"(p));
    return a;
}
__device__ __forceinline__ void cp_async16(uint32_t dst, const void* src, int nbytes) {
    asm volatile("cp.async.cg.shared.global [%0], [%1], 16, %2;"
                 :: "r"(dst), "l"(src), "r"(nbytes) : "memory");
}
__device__ __forceinline__ void cp_commit() {
    asm volatile("cp.async.commit_group;" ::: "memory");
}
__device__ __forceinline__ void cp_wait0() {
    asm volatile("cp.async.wait_group 0;" ::: "memory");
}

// ---------------- init: zero cnt, deg=1, split-bf16 weights ----------------
__global__ void init_misc(const float* __restrict__ Wp1,
                          const float* __restrict__ W1,
                          const float* __restrict__ W2) {
    if (blockIdx.x < NPART) {
        int i = blockIdx.x * 256 + threadIdx.x;
        if (i < NN) { g_cnt[i] = 0; g_deg[i] = 1.0f; }
        return;
    }
    int idx = (blockIdx.x - NPART) * 256 + threadIdx.x;   // 3*8192 pairs
    if (idx >= 3 * 8192) return;
    int m  = idx >> 13;
    int p  = idx & 8191;
    int n  = p >> 6;
    int k  = (p & 63) * 2;
    float f0, f1;
    if (m == 0) {
        f0 = (n < 64) ? Wp1[n * 256 + k]     : Wp1[(n - 64) * 256 + 128 + k];
        f1 = (n < 64) ? Wp1[n * 256 + k + 1] : Wp1[(n - 64) * 256 + 128 + k + 1];
    } else if (m == 1) { f0 = W1[n * 128 + k]; f1 = W1[n * 128 + k + 1]; }
    else               { f0 = W2[n * 128 + k]; f1 = W2[n * 128 + k + 1]; }
    __nv_bfloat162 h = __floats2bfloat162_rn(f0, f1);
    __nv_bfloat162 l = __floats2bfloat162_rn(f0 - __bfloat162float(h.x),
                                             f1 - __bfloat162float(h.y));
    g_Bhi[m][p] = *(unsigned*)&h;
    g_Blo[m][p] = *(unsigned*)&l;
}

// ---------------- split-bf16 HMMA GEMM, cp.async pipelined, fp16 output -------
// Yh[M,128] = fp16(X[M,128] @ B^T). 32-row tiles. smem (words):
//   stage 4096 | Ah 32*68 | Al 32*68 | Bh 128*68 | Bl 128*68  = 103424 B
#define RS 68
__global__ void __launch_bounds__(256, 2)
gemm_mma(const float* __restrict__ X, const unsigned* __restrict__ Bhi,
         const unsigned* __restrict__ Blo, __half* __restrict__ Yh, int M) {
    extern __shared__ unsigned sm[];
    float*    St = (float*)sm;                 // 4096 words
    unsigned* Ah = sm + 4096;                  // 32*RS
    unsigned* Al = sm + 4096 + 32 * RS;        // 32*RS
    unsigned* Bh = sm + 4096 + 64 * RS;        // 128*RS
    unsigned* Bl = sm + 4096 + 64 * RS + 128 * RS;
    const uint32_t st_base = smem_u32(St);

    const int tid  = threadIdx.x;
    const int lane = tid & 31;
    const int warp = tid >> 5;
    const int wm = warp & 1;     // 2 m-groups of 16 rows
    const int wn = warp >> 1;    // 4 n-groups of 32 cols
    const int g  = lane >> 2;
    const int tg = lane & 3;

    const int ntiles = (M + 31) >> 5;
    int tile = blockIdx.x;

    // prime: issue cp.async for first tile (overlaps B staging below)
    if (tile < ntiles) {
        #pragma unroll
        for (int k = 0; k < 4; k++) {
            int idx = tid + k * 256;           // float4 units
            int r = idx >> 5, c4 = idx & 31;
            int gr = (tile << 5) + r;
            cp_async16(st_base + idx * 16,
                       X + (size_t)gr * 128 + c4 * 4,
                       (gr < M) ? 16 : 0);
        }
    }
    cp_commit();

    // stage weights (hi+lo)
    #pragma unroll 4
    for (int i = tid; i < 8192; i += 256) {
        int n = i >> 6, cp = i & 63;
        Bh[n * RS + cp] = Bhi[i];
        Bl[n * RS + cp] = Blo[i];
    }

    for (; tile < ntiles; tile += gridDim.x) {
        const int row0 = tile << 5;
        cp_wait0();
        __syncthreads();   // stage ready; prev MMA reads of Ah/Al done

        // convert stage -> Ah/Al (smem only)
        #pragma unroll
        for (int k = 0; k < 8; k++) {
            int idx = tid + k * 256;           // float2 units: 32*64
            int r = idx >> 6, cp = idx & 63;
            float2 f = *(const float2*)&St[idx * 2];
            __nv_bfloat162 h = __floats2bfloat162_rn(f.x, f.y);
            __nv_bfloat162 l = __floats2bfloat162_rn(f.x - __bfloat162float(h.x),
                                                     f.y - __bfloat162float(h.y));
            Ah[r * RS + cp] = *(unsigned*)&h;
            Al[r * RS + cp] = *(unsigned*)&l;
        }
        __syncthreads();   // Ah/Al ready; stage reads done -> safe to refill

        // prefetch next tile into stage (hidden behind MMA below)
        int nxt = tile + gridDim.x;
        if (nxt < ntiles) {
            #pragma unroll
            for (int k = 0; k < 4; k++) {
                int idx = tid + k * 256;
                int r = idx >> 5, c4 = idx & 31;
                int gr = (nxt << 5) + r;
                cp_async16(st_base + idx * 16,
                           X + (size_t)gr * 128 + c4 * 4,
                           (gr < M) ? 16 : 0);
            }
        }
        cp_commit();

        float acc[4][4];
        #pragma unroll
        for (int nt = 0; nt < 4; nt++)
            #pragma unroll
            for (int q = 0; q < 4; q++) acc[nt][q] = 0.f;

        #pragma unroll
        for (int kc = 0; kc < 8; kc++) {
            unsigned ah[4], al[4];
            int w0 = (wm * 16 + g) * RS + kc * 8 + tg;
            ah[0] = Ah[w0];
            ah[1] = Ah[w0 + 8 * RS];
            ah[2] = Ah[w0 + 4];
            ah[3] = Ah[w0 + 8 * RS + 4];
            al[0] = Al[w0];
            al[1] = Al[w0 + 8 * RS];
            al[2] = Al[w0 + 4];
            al[3] = Al[w0 + 8 * RS + 4];
            #pragma unroll
            for (int nt = 0; nt < 4; nt++) {
                int nb = (wn * 32 + nt * 8 + g) * RS + kc * 8 + tg;
                unsigned bh0 = Bh[nb], bh1 = Bh[nb + 4];
                unsigned bl0 = Bl[nb], bl1 = Bl[nb + 4];
                mma_bf16(acc[nt], ah, bh0, bh1);   // hi*hi
                mma_bf16(acc[nt], ah, bl0, bl1);   // hi*lo
                mma_bf16(acc[nt], al, bh0, bh1);   // lo*hi
            }
        }

        // epilogue: fp16 output only
        int r = row0 + wm * 16 + g;
        #pragma unroll
        for (int nt = 0; nt < 4; nt++) {
            int c = wn * 32 + nt * 8 + tg * 2;
            if (r < M)
                *(__half2*)&Yh[(size_t)r * 128 + c] =
                    __floats2half2_rn(acc[nt][0], acc[nt][1]);
            if (r + 8 < M)
                *(__half2*)&Yh[(size_t)(r + 8) * 128 + c] =
                    __floats2half2_rn(acc[nt][2], acc[nt][3]);
        }
    }
}

// ---------------- edge conversion (dtype-robust) + dst histogram ----------------
__global__ void convert_edges(const int* __restrict__ raw) {
    bool is64 = true;
    #pragma unroll
    for (int i = 1; i < 128; i += 2)
        if (raw[i] != 0) { is64 = false; break; }
    int e = blockIdx.x * blockDim.x + threadIdx.x;
    if (e >= EE) return;
    int s, d;
    if (is64) { s = raw[2 * e];  d = raw[2 * (EE + e)]; }
    else      { s = raw[e];      d = raw[EE + e]; }
    g_src[e] = s;
    g_dst[e] = d;
    atomicAdd(&g_cnt[d], 1);
}

// ---------------- 3-kernel exclusive scan ----------------
__global__ void scan_part() {
    __shared__ int sm[256];
    int tid = threadIdx.x;
    int i = blockIdx.x * 256 + tid;
    sm[tid] = (i < NN) ? g_cnt[i] : 0;
    __syncthreads();
    for (int o = 128; o; o >>= 1) {
        if (tid < o) sm[tid] += sm[tid + o];
        __syncthreads();
    }
    if (tid == 0) g_part[blockIdx.x] = sm[0];
}

__global__ void scan_tops() {
    __shared__ int sm[256];
    int tid = threadIdx.x;
    int v = (tid < NPART) ? g_part[tid] : 0;
    sm[tid] = v;
    __syncthreads();
    for (int o = 1; o < 256; o <<= 1) {
        int t = sm[tid] + ((tid >= o) ? sm[tid - o] : 0);
        __syncthreads();
        sm[tid] = t;
        __syncthreads();
    }
    if (tid < NPART) g_part[tid] = sm[tid] - v;
}

__global__ void scan_final() {
    __shared__ int sm[256];
    int tid = threadIdx.x;
    int i = blockIdx.x * 256 + tid;
    int v = (i < NN) ? g_cnt[i] : 0;
    sm[tid] = v;
    __syncthreads();
    for (int o = 1; o < 256; o <<= 1) {
        int t = sm[tid] + ((tid >= o) ? sm[tid - o] : 0);
        __syncthreads();
        sm[tid] = t;
        __syncthreads();
    }
    if (i < NN) {
        int excl = sm[tid] - v + g_part[blockIdx.x];
        g_row[i] = excl;
        g_cur[i] = excl;
    }
    if (i == 0) g_row[NN] = EE;
}

// ------- fused edge pass (fp16 gathers): ew; CSR fill; deg ---------------------
__global__ void edge_fused(const float* __restrict__ b_p1,
                           const float* __restrict__ W_p2,
                           const float* __restrict__ b_p2) {
    int e = (blockIdx.x * blockDim.x + threadIdx.x) >> 5;
    int lane = threadIdx.x & 31;
    if (e >= EE) return;
    int s = g_src[e];
    int d = g_dst[e];
    float2 a  = __half22float2(*(const __half2*)&g_ABh[(size_t)s * 128 + lane * 2]);
    float2 b  = __half22float2(*(const __half2*)&g_ABh[(size_t)d * 128 + 64 + lane * 2]);
    float2 bp = *(const float2*)&b_p1[lane * 2];
    float2 w2 = *(const float2*)&W_p2[lane * 2];
    float h0 = fmaxf(a.x + b.x + bp.x, 0.f);
    float h1 = fmaxf(a.y + b.y + bp.y, 0.f);
    float p = h0 * w2.x + h1 * w2.y;
    #pragma unroll
    for (int o = 16; o; o >>= 1) p += __shfl_xor_sync(0xffffffffu, p, o);
    if (lane == 0) {
        float v = 1.f / (1.f + expf(-(p + b_p2[0])));
        int slot = atomicAdd(&g_cur[d], 1);
        g_csrc[slot] = s;
        g_cw[slot]   = v;
        atomicAdd(&g_deg[d], v);
    }
}

// ---------------- fused dinv + coef: per node ----------------
__global__ void dinv_coef() {
    int n = blockIdx.x * blockDim.x + threadIdx.x;
    if (n >= NN) return;
    float dd = rsqrtf(g_deg[n]);
    g_dinv[n] = dd;
    int e0 = g_row[n], e1 = g_row[n + 1];
    for (int j = e0; j < e1; j++)
        g_cw[j] *= dd * rsqrtf(g_deg[g_csrc[j]]);
}

// ---------------- conv (fp16 gather) + relu -> fp32 x1 ----------------
__global__ void conv_relu(const float* __restrict__ bias) {
    int n = blockIdx.x;
    int f = threadIdx.x;
    float di = g_dinv[n];
    float acc = bias[f] + di * di * __half2float(g_xlh[(size_t)n * 128 + f]);
    int e0 = g_row[n], e1 = g_row[n + 1];
    for (int j = e0; j < e1; j++) {
        int s = g_csrc[j];
        float c = g_cw[j];
        acc += c * __half2float(g_xlh[(size_t)s * 128 + f]);
    }
    g_x1[(size_t)n * 128 + f] = fmaxf(acc, 0.f);
}

// ---------------- conv2 (fp16 gather) + fused head ----------------
__global__ void conv_head(const float* __restrict__ bias,
                          const float* __restrict__ W_lin,
                          const float* __restrict__ b_lin,
                          float* __restrict__ out) {
    int n = blockIdx.x;
    int f = threadIdx.x;
    float di = g_dinv[n];
    float acc = bias[f] + di * di * __half2float(g_xlh[(size_t)n * 128 + f]);
    int e0 = g_row[n], e1 = g_row[n + 1];
    for (int j = e0; j < e1; j++) {
        int s = g_csrc[j];
        float c = g_cw[j];
        acc += c * __half2float(g_xlh[(size_t)s * 128 + f]);
    }
    float v = fmaxf(acc, 0.f);
    __shared__ float2 red[128];
    red[f] = make_float2(v * W_lin[f], v * W_lin[128 + f]);
    __syncthreads();
    #pragma unroll
    for (int o = 64; o; o >>= 1) {
        if (f < o) {
            red[f].x += red[f + o].x;
            red[f].y += red[f + o].y;
        }
        __syncthreads();
    }
    if (f == 0) {
        out[2 * n + 0] = 1.f / (1.f + expf(-(red[0].x + b_lin[0])));
        out[2 * n + 1] = 1.f / (1.f + expf(-(red[0].y + b_lin[1])));
    }
}

// ---------------- host ----------------
extern "C" void kernel_launch(void* const* d_in, const int* in_sizes, int n_in,
                              void* d_out, int out_size) {
    const float* x     = (const float*)d_in[0];
    const int*   ei    = (const int*)d_in[1];
    const float* W_p1  = (const float*)d_in[2];
    const float* b_p1  = (const float*)d_in[3];
    const float* W_p2  = (const float*)d_in[4];
    const float* b_p2  = (const float*)d_in[5];
    const float* W1    = (const float*)d_in[6];
    const float* b1    = (const float*)d_in[7];
    const float* W2    = (const float*)d_in[8];
    const float* b2    = (const float*)d_in[9];
    const float* W_lin = (const float*)d_in[10];
    const float* b_lin = (const float*)d_in[11];
    float* out = (float*)d_out;

    void *pABh, *pXLh, *pX1, *pBhi, *pBlo;
    cudaGetSymbolAddress(&pABh, g_ABh);
    cudaGetSymbolAddress(&pXLh, g_xlh);
    cudaGetSymbolAddress(&pX1,  g_x1);
    cudaGetSymbolAddress(&pBhi, g_Bhi);
    cudaGetSymbolAddress(&pBlo, g_Blo);
    const unsigned* Bhi = (const unsigned*)pBhi;
    const unsigned* Blo = (const unsigned*)pBlo;

    const int MMA_SMEM = (4096 + 64 * RS + 256 * RS) * 4;  // 103424 B -> 2 CTAs/SM
    cudaFuncSetAttribute(gemm_mma, cudaFuncAttributeMaxDynamicSharedMemorySize, MMA_SMEM);

    const int GRID        = 296;
    const int edge_blocks = (EE * 32 + 255) / 256;
    const int e_blocks    = (EE + 255) / 256;
    const int n_blocks    = (NN + 255) / 256;

    init_misc<<<NPART + 96, 256>>>(W_p1, W1, W2);                         // 0
    convert_edges<<<e_blocks, 256>>>(ei);                                 // 1
    scan_part<<<NPART, 256>>>();                                          // 2
    gemm_mma<<<GRID, 256, MMA_SMEM>>>(x, Bhi, Blo, (__half*)pABh, NN);    // 3 (profiled)
    scan_tops<<<1, 256>>>();                                              // 4
    scan_final<<<NPART, 256>>>();                                         // 5
    edge_fused<<<edge_blocks, 256>>>(b_p1, W_p2, b_p2);                   // 6
    dinv_coef<<<n_blocks, 256>>>();                                       // 7
    gemm_mma<<<GRID, 256, MMA_SMEM>>>(x, Bhi + 8192, Blo + 8192,
                                      (__half*)pXLh, NN);                 // 8
    conv_relu<<<NN, 128>>>(b1);                                           // 9
    gemm_mma<<<GRID, 256, MMA_SMEM>>>((const float*)pX1, Bhi + 16384,
                                      Blo + 16384, (__half*)pXLh, NN);    // 10
    conv_head<<<NN, 128>>>(b2, W_lin, b_lin, out);                        // 11
}

// round 13
// speedup vs baseline: 1.5652x; 1.5239x over previous
#include <cuda_runtime.h>
#include <cuda_bf16.h>
#include <cuda_fp16.h>
#include <cstdint>

#define NN 50000
#define EE 600000
#define NPART 196   // ceil(NN/256)

// ---------------- device scratch ----------------
__device__ __align__(16) float  g_deg[NN];
__device__ __align__(16) float  g_dinv[NN];
__device__ __align__(16) __half g_ABh[NN * 128];   // edge-MLP table (fp16)
__device__ __align__(16) __half g_xlh[NN * 128];   // conv message table (fp16)
__device__ __align__(16) float  g_x1[NN * 128];    // conv1 output (fp32, GEMM input)
__device__ __align__(16) int    g_src[EE];
__device__ __align__(16) int    g_dst[EE];
__device__ __align__(16) int    g_cnt[NN];
__device__ __align__(16) int    g_part[256];
__device__ __align__(16) int    g_row[NN + 1];
__device__ __align__(16) int    g_cur[NN];
__device__ __align__(16) int    g_csrc[EE];
__device__ __align__(16) float  g_cw[EE];
// bf16 hi/lo weights, row-major packed bf16x2: [mat][n*64 + colpair]
__device__ __align__(16) unsigned g_Bhi[3][8192];
__device__ __align__(16) unsigned g_Blo[3][8192];

// ---------------- PTX helpers (base PTX only) ----------------
__device__ __forceinline__ void mma_bf16(float* c, const unsigned* a,
                                         unsigned b0, unsigned b1) {
    asm volatile(
        "mma.sync.aligned.m16n8k16.row.col.f32.bf16.bf16.f32 "
        "{%0,%1,%2,%3}, {%4,%5,%6,%7}, {%8,%9}, {%0,%1,%2,%3};"
        : "+f"(c[0]), "+f"(c[1]), "+f"(c[2]), "+f"(c[3])
        : "r"(a[0]), "r"(a[1]), "r"(a[2]), "r"(a[3]), "r"(b0), "r"(b1));
}
__device__ __forceinline__ uint32_t smem_u32(const void* p) {
    uint32_t a;
    asm("{ .reg .u64 t; cvta.to.shared.u64 t, %1; cvt.u32.u64 %0, t; }"
        : "=r"(a) : "l"(p));
    return a;
}
__device__ __forceinline__ void cp_async16(uint32_t dst, const void* src, int nbytes) {
    asm volatile("cp.async.cg.shared.global [%0], [%1], 16, %2;"
                 :: "r"(dst), "l"(src), "r"(nbytes) : "memory");
}
__device__ __forceinline__ void cp_commit() {
    asm volatile("cp.async.commit_group;" ::: "memory");
}
__device__ __forceinline__ void cp_wait0() {
    asm volatile("cp.async.wait_group 0;" ::: "memory");
}
// gather 4 features (uint2 = 4 halves) from a table row
__device__ __forceinline__ float4 row4(const __half* tab, int s, int f4) {
    uint2 u = *(const uint2*)&tab[(size_t)s * 128 + f4];
    float2 f01 = __half22float2(*(__half2*)&u.x);
    float2 f23 = __half22float2(*(__half2*)&u.y);
    return make_float4(f01.x, f01.y, f23.x, f23.y);
}

// ---------------- init: zero cnt, deg=1, split-bf16 weights ----------------
__global__ void init_misc(const float* __restrict__ Wp1,
                          const float* __restrict__ W1,
                          const float* __restrict__ W2) {
    if (blockIdx.x < NPART) {
        int i = blockIdx.x * 256 + threadIdx.x;
        if (i < NN) { g_cnt[i] = 0; g_deg[i] = 1.0f; }
        return;
    }
    int idx = (blockIdx.x - NPART) * 256 + threadIdx.x;   // 3*8192 pairs
    if (idx >= 3 * 8192) return;
    int m  = idx >> 13;
    int p  = idx & 8191;
    int n  = p >> 6;
    int k  = (p & 63) * 2;
    float f0, f1;
    if (m == 0) {
        f0 = (n < 64) ? Wp1[n * 256 + k]     : Wp1[(n - 64) * 256 + 128 + k];
        f1 = (n < 64) ? Wp1[n * 256 + k + 1] : Wp1[(n - 64) * 256 + 128 + k + 1];
    } else if (m == 1) { f0 = W1[n * 128 + k]; f1 = W1[n * 128 + k + 1]; }
    else               { f0 = W2[n * 128 + k]; f1 = W2[n * 128 + k + 1]; }
    __nv_bfloat162 h = __floats2bfloat162_rn(f0, f1);
    __nv_bfloat162 l = __floats2bfloat162_rn(f0 - __bfloat162float(h.x),
                                             f1 - __bfloat162float(h.y));
    g_Bhi[m][p] = *(unsigned*)&h;
    g_Blo[m][p] = *(unsigned*)&l;
}

// ---------------- split-bf16 HMMA GEMM, cp.async pipelined, fp16 output -------
#define RS 68
__global__ void __launch_bounds__(256, 2)
gemm_mma(const float* __restrict__ X, const unsigned* __restrict__ Bhi,
         const unsigned* __restrict__ Blo, __half* __restrict__ Yh, int M) {
    extern __shared__ unsigned sm[];
    float*    St = (float*)sm;                 // 4096 words
    unsigned* Ah = sm + 4096;                  // 32*RS
    unsigned* Al = sm + 4096 + 32 * RS;        // 32*RS
    unsigned* Bh = sm + 4096 + 64 * RS;        // 128*RS
    unsigned* Bl = sm + 4096 + 64 * RS + 128 * RS;
    const uint32_t st_base = smem_u32(St);

    const int tid  = threadIdx.x;
    const int lane = tid & 31;
    const int warp = tid >> 5;
    const int wm = warp & 1;
    const int wn = warp >> 1;
    const int g  = lane >> 2;
    const int tg = lane & 3;

    const int ntiles = (M + 31) >> 5;
    int tile = blockIdx.x;

    if (tile < ntiles) {
        #pragma unroll
        for (int k = 0; k < 4; k++) {
            int idx = tid + k * 256;
            int r = idx >> 5, c4 = idx & 31;
            int gr = (tile << 5) + r;
            cp_async16(st_base + idx * 16,
                       X + (size_t)gr * 128 + c4 * 4,
                       (gr < M) ? 16 : 0);
        }
    }
    cp_commit();

    #pragma unroll 4
    for (int i = tid; i < 8192; i += 256) {
        int n = i >> 6, cp = i & 63;
        Bh[n * RS + cp] = Bhi[i];
        Bl[n * RS + cp] = Blo[i];
    }

    for (; tile < ntiles; tile += gridDim.x) {
        const int row0 = tile << 5;
        cp_wait0();
        __syncthreads();

        #pragma unroll
        for (int k = 0; k < 8; k++) {
            int idx = tid + k * 256;
            int r = idx >> 6, cp = idx & 63;
            float2 f = *(const float2*)&St[idx * 2];
            __nv_bfloat162 h = __floats2bfloat162_rn(f.x, f.y);
            __nv_bfloat162 l = __floats2bfloat162_rn(f.x - __bfloat162float(h.x),
                                                     f.y - __bfloat162float(h.y));
            Ah[r * RS + cp] = *(unsigned*)&h;
            Al[r * RS + cp] = *(unsigned*)&l;
        }
        __syncthreads();

        int nxt = tile + gridDim.x;
        if (nxt < ntiles) {
            #pragma unroll
            for (int k = 0; k < 4; k++) {
                int idx = tid + k * 256;
                int r = idx >> 5, c4 = idx & 31;
                int gr = (nxt << 5) + r;
                cp_async16(st_base + idx * 16,
                           X + (size_t)gr * 128 + c4 * 4,
                           (gr < M) ? 16 : 0);
            }
        }
        cp_commit();

        float acc[4][4];
        #pragma unroll
        for (int nt = 0; nt < 4; nt++)
            #pragma unroll
            for (int q = 0; q < 4; q++) acc[nt][q] = 0.f;

        #pragma unroll
        for (int kc = 0; kc < 8; kc++) {
            unsigned ah[4], al[4];
            int w0 = (wm * 16 + g) * RS + kc * 8 + tg;
            ah[0] = Ah[w0];
            ah[1] = Ah[w0 + 8 * RS];
            ah[2] = Ah[w0 + 4];
            ah[3] = Ah[w0 + 8 * RS + 4];
            al[0] = Al[w0];
            al[1] = Al[w0 + 8 * RS];
            al[2] = Al[w0 + 4];
            al[3] = Al[w0 + 8 * RS + 4];
            #pragma unroll
            for (int nt = 0; nt < 4; nt++) {
                int nb = (wn * 32 + nt * 8 + g) * RS + kc * 8 + tg;
                unsigned bh0 = Bh[nb], bh1 = Bh[nb + 4];
                unsigned bl0 = Bl[nb], bl1 = Bl[nb + 4];
                mma_bf16(acc[nt], ah, bh0, bh1);
                mma_bf16(acc[nt], ah, bl0, bl1);
                mma_bf16(acc[nt], al, bh0, bh1);
            }
        }

        int r = row0 + wm * 16 + g;
        #pragma unroll
        for (int nt = 0; nt < 4; nt++) {
            int c = wn * 32 + nt * 8 + tg * 2;
            if (r < M)
                *(__half2*)&Yh[(size_t)r * 128 + c] =
                    __floats2half2_rn(acc[nt][0], acc[nt][1]);
            if (r + 8 < M)
                *(__half2*)&Yh[(size_t)(r + 8) * 128 + c] =
                    __floats2half2_rn(acc[nt][2], acc[nt][3]);
        }
    }
}

// ---------------- edge conversion (dtype-robust) + dst histogram ----------------
__global__ void convert_edges(const int* __restrict__ raw) {
    bool is64 = true;
    #pragma unroll
    for (int i = 1; i < 128; i += 2)
        if (raw[i] != 0) { is64 = false; break; }
    int e = blockIdx.x * blockDim.x + threadIdx.x;
    if (e >= EE) return;
    int s, d;
    if (is64) { s = raw[2 * e];  d = raw[2 * (EE + e)]; }
    else      { s = raw[e];      d = raw[EE + e]; }
    g_src[e] = s;
    g_dst[e] = d;
    atomicAdd(&g_cnt[d], 1);
}

// ---------------- 3-kernel exclusive scan ----------------
__global__ void scan_part() {
    __shared__ int sm[256];
    int tid = threadIdx.x;
    int i = blockIdx.x * 256 + tid;
    sm[tid] = (i < NN) ? g_cnt[i] : 0;
    __syncthreads();
    for (int o = 128; o; o >>= 1) {
        if (tid < o) sm[tid] += sm[tid + o];
        __syncthreads();
    }
    if (tid == 0) g_part[blockIdx.x] = sm[0];
}

__global__ void scan_tops() {
    __shared__ int sm[256];
    int tid = threadIdx.x;
    int v = (tid < NPART) ? g_part[tid] : 0;
    sm[tid] = v;
    __syncthreads();
    for (int o = 1; o < 256; o <<= 1) {
        int t = sm[tid] + ((tid >= o) ? sm[tid - o] : 0);
        __syncthreads();
        sm[tid] = t;
        __syncthreads();
    }
    if (tid < NPART) g_part[tid] = sm[tid] - v;
}

__global__ void scan_final() {
    __shared__ int sm[256];
    int tid = threadIdx.x;
    int i = blockIdx.x * 256 + tid;
    int v = (i < NN) ? g_cnt[i] : 0;
    sm[tid] = v;
    __syncthreads();
    for (int o = 1; o < 256; o <<= 1) {
        int t = sm[tid] + ((tid >= o) ? sm[tid - o] : 0);
        __syncthreads();
        sm[tid] = t;
        __syncthreads();
    }
    if (i < NN) {
        int excl = sm[tid] - v + g_part[blockIdx.x];
        g_row[i] = excl;
        g_cur[i] = excl;
    }
    if (i == 0) g_row[NN] = EE;
}

// ------- fused edge pass: 2 edges per warp (16-lane halves) --------------------
__global__ void edge_fused(const float* __restrict__ b_p1,
                           const float* __restrict__ W_p2,
                           const float* __restrict__ b_p2) {
    int gw = (blockIdx.x * blockDim.x + threadIdx.x) >> 5;
    int lane = threadIdx.x & 31;
    int half = lane >> 4;          // which edge in this warp
    int hl = lane & 15;            // lane within half: 4 hidden units
    int e = gw * 2 + half;
    if (e >= EE) return;
    int s = g_src[e];
    int d = g_dst[e];
    float4 a  = row4(g_ABh, s, hl * 4);
    uint2 ub  = *(const uint2*)&g_ABh[(size_t)d * 128 + 64 + hl * 4];
    float2 b01 = __half22float2(*(__half2*)&ub.x);
    float2 b23 = __half22float2(*(__half2*)&ub.y);
    float4 bp = *(const float4*)&b_p1[hl * 4];
    float4 w2 = *(const float4*)&W_p2[hl * 4];
    float h0 = fmaxf(a.x + b01.x + bp.x, 0.f);
    float h1 = fmaxf(a.y + b01.y + bp.y, 0.f);
    float h2 = fmaxf(a.z + b23.x + bp.z, 0.f);
    float h3 = fmaxf(a.w + b23.y + bp.w, 0.f);
    float p = h0 * w2.x + h1 * w2.y + h2 * w2.z + h3 * w2.w;
    #pragma unroll
    for (int o = 8; o; o >>= 1) p += __shfl_xor_sync(0xffffffffu, p, o);
    if (hl == 0) {
        float v = 1.f / (1.f + expf(-(p + b_p2[0])));
        int slot = atomicAdd(&g_cur[d], 1);
        g_csrc[slot] = s;
        g_cw[slot]   = v;
        atomicAdd(&g_deg[d], v);
    }
}

// ---------------- fused dinv + coef: per node ----------------
__global__ void dinv_coef() {
    int n = blockIdx.x * blockDim.x + threadIdx.x;
    if (n >= NN) return;
    float dd = rsqrtf(g_deg[n]);
    g_dinv[n] = dd;
    int e0 = g_row[n], e1 = g_row[n + 1];
    for (int j = e0; j < e1; j++)
        g_cw[j] *= dd * rsqrtf(g_deg[g_csrc[j]]);
}

// ---------------- conv1: warp per node, 4x unrolled gather, relu -> fp32 ------
__global__ void conv_relu(const float* __restrict__ bias) {
    int n = blockIdx.x * 8 + (threadIdx.x >> 5);
    int lane = threadIdx.x & 31;
    if (n >= NN) return;
    int f4 = lane * 4;
    float di = g_dinv[n];
    float c0 = di * di;
    float4 b4 = *(const float4*)&bias[f4];
    float4 x0 = row4(g_xlh, n, f4);
    float a0 = b4.x + c0 * x0.x;
    float a1 = b4.y + c0 * x0.y;
    float a2 = b4.z + c0 * x0.z;
    float a3 = b4.w + c0 * x0.w;
    int e0 = g_row[n], e1 = g_row[n + 1];
    int j = e0;
    for (; j + 4 <= e1; j += 4) {
        int s0 = g_csrc[j], s1 = g_csrc[j + 1], s2 = g_csrc[j + 2], s3 = g_csrc[j + 3];
        float w0 = g_cw[j], w1 = g_cw[j + 1], w2 = g_cw[j + 2], w3 = g_cw[j + 3];
        float4 r0 = row4(g_xlh, s0, f4);
        float4 r1 = row4(g_xlh, s1, f4);
        float4 r2 = row4(g_xlh, s2, f4);
        float4 r3 = row4(g_xlh, s3, f4);
        a0 += w0 * r0.x + w1 * r1.x + w2 * r2.x + w3 * r3.x;
        a1 += w0 * r0.y + w1 * r1.y + w2 * r2.y + w3 * r3.y;
        a2 += w0 * r0.z + w1 * r1.z + w2 * r2.z + w3 * r3.z;
        a3 += w0 * r0.w + w1 * r1.w + w2 * r2.w + w3 * r3.w;
    }
    for (; j < e1; j++) {
        int s = g_csrc[j];
        float w = g_cw[j];
        float4 r = row4(g_xlh, s, f4);
        a0 += w * r.x; a1 += w * r.y; a2 += w * r.z; a3 += w * r.w;
    }
    *(float4*)&g_x1[(size_t)n * 128 + f4] =
        make_float4(fmaxf(a0, 0.f), fmaxf(a1, 0.f), fmaxf(a2, 0.f), fmaxf(a3, 0.f));
}

// ---------------- conv2 + head: warp per node, shuffle reduction ----------------
__global__ void conv_head(const float* __restrict__ bias,
                          const float* __restrict__ W_lin,
                          const float* __restrict__ b_lin,
                          float* __restrict__ out) {
    int n = blockIdx.x * 8 + (threadIdx.x >> 5);
    int lane = threadIdx.x & 31;
    if (n >= NN) return;
    int f4 = lane * 4;
    float di = g_dinv[n];
    float c0 = di * di;
    float4 b4 = *(const float4*)&bias[f4];
    float4 x0 = row4(g_xlh, n, f4);
    float a0 = b4.x + c0 * x0.x;
    float a1 = b4.y + c0 * x0.y;
    float a2 = b4.z + c0 * x0.z;
    float a3 = b4.w + c0 * x0.w;
    int e0 = g_row[n], e1 = g_row[n + 1];
    int j = e0;
    for (; j + 4 <= e1; j += 4) {
        int s0 = g_csrc[j], s1 = g_csrc[j + 1], s2 = g_csrc[j + 2], s3 = g_csrc[j + 3];
        float w0 = g_cw[j], w1 = g_cw[j + 1], w2 = g_cw[j + 2], w3 = g_cw[j + 3];
        float4 r0 = row4(g_xlh, s0, f4);
        float4 r1 = row4(g_xlh, s1, f4);
        float4 r2 = row4(g_xlh, s2, f4);
        float4 r3 = row4(g_xlh, s3, f4);
        a0 += w0 * r0.x + w1 * r1.x + w2 * r2.x + w3 * r3.x;
        a1 += w0 * r0.y + w1 * r1.y + w2 * r2.y + w3 * r3.y;
        a2 += w0 * r0.z + w1 * r1.z + w2 * r2.z + w3 * r3.z;
        a3 += w0 * r0.w + w1 * r1.w + w2 * r2.w + w3 * r3.w;
    }
    for (; j < e1; j++) {
        int s = g_csrc[j];
        float w = g_cw[j];
        float4 r = row4(g_xlh, s, f4);
        a0 += w * r.x; a1 += w * r.y; a2 += w * r.z; a3 += w * r.w;
    }
    float v0 = fmaxf(a0, 0.f), v1 = fmaxf(a1, 0.f);
    float v2 = fmaxf(a2, 0.f), v3 = fmaxf(a3, 0.f);
    float4 wl0 = *(const float4*)&W_lin[f4];
    float4 wl1 = *(const float4*)&W_lin[128 + f4];
    float p0 = v0 * wl0.x + v1 * wl0.y + v2 * wl0.z + v3 * wl0.w;
    float p1 = v0 * wl1.x + v1 * wl1.y + v2 * wl1.z + v3 * wl1.w;
    #pragma unroll
    for (int o = 16; o; o >>= 1) {
        p0 += __shfl_xor_sync(0xffffffffu, p0, o);
        p1 += __shfl_xor_sync(0xffffffffu, p1, o);
    }
    if (lane == 0) {
        out[2 * n + 0] = 1.f / (1.f + expf(-(p0 + b_lin[0])));
        out[2 * n + 1] = 1.f / (1.f + expf(-(p1 + b_lin[1])));
    }
}

// ---------------- host ----------------
extern "C" void kernel_launch(void* const* d_in, const int* in_sizes, int n_in,
                              void* d_out, int out_size) {
    const float* x     = (const float*)d_in[0];
    const int*   ei    = (const int*)d_in[1];
    const float* W_p1  = (const float*)d_in[2];
    const float* b_p1  = (const float*)d_in[3];
    const float* W_p2  = (const float*)d_in[4];
    const float* b_p2  = (const float*)d_in[5];
    const float* W1    = (const float*)d_in[6];
    const float* b1    = (const float*)d_in[7];
    const float* W2    = (const float*)d_in[8];
    const float* b2    = (const float*)d_in[9];
    const float* W_lin = (const float*)d_in[10];
    const float* b_lin = (const float*)d_in[11];
    float* out = (float*)d_out;

    void *pABh, *pXLh, *pX1, *pBhi, *pBlo;
    cudaGetSymbolAddress(&pABh, g_ABh);
    cudaGetSymbolAddress(&pXLh, g_xlh);
    cudaGetSymbolAddress(&pX1,  g_x1);
    cudaGetSymbolAddress(&pBhi, g_Bhi);
    cudaGetSymbolAddress(&pBlo, g_Blo);
    const unsigned* Bhi = (const unsigned*)pBhi;
    const unsigned* Blo = (const unsigned*)pBlo;

    const int MMA_SMEM = (4096 + 64 * RS + 256 * RS) * 4;  // 103424 B -> 2 CTAs/SM
    cudaFuncSetAttribute(gemm_mma, cudaFuncAttributeMaxDynamicSharedMemorySize, MMA_SMEM);

    const int GRID        = 296;
    const int edge_blocks = (EE / 2 + 7) / 8;      // 2 edges/warp, 8 warps/block
    const int e_blocks    = (EE + 255) / 256;
    const int n_blocks    = (NN + 255) / 256;
    const int conv_blocks = (NN + 7) / 8;          // warp per node

    init_misc<<<NPART + 96, 256>>>(W_p1, W1, W2);                         // 0
    convert_edges<<<e_blocks, 256>>>(ei);                                 // 1
    scan_part<<<NPART, 256>>>();                                          // 2
    gemm_mma<<<GRID, 256, MMA_SMEM>>>(x, Bhi, Blo, (__half*)pABh, NN);    // 3 (profiled)
    scan_tops<<<1, 256>>>();                                              // 4
    scan_final<<<NPART, 256>>>();                                         // 5
    edge_fused<<<edge_blocks, 256>>>(b_p1, W_p2, b_p2);                   // 6
    dinv_coef<<<n_blocks, 256>>>();                                       // 7
    gemm_mma<<<GRID, 256, MMA_SMEM>>>(x, Bhi + 8192, Blo + 8192,
                                      (__half*)pXLh, NN);                 // 8
    conv_relu<<<conv_blocks, 256>>>(b1);                                  // 9
    gemm_mma<<<GRID, 256, MMA_SMEM>>>((const float*)pX1, Bhi + 16384,
                                      Blo + 16384, (__half*)pXLh, NN);    // 10
    conv_head<<<conv_blocks, 256>>>(b2, W_lin, b_lin, out);               // 11
}